// round 4
// baseline (speedup 1.0000x reference)
#include <cuda_runtime.h>
#include <cstdint>

#define NN 50000
#define NE 600000
#define CH 128

// ---------------- scratch (static device globals; no allocation) ----------------
__device__ float    g_sum[NN*CH];       // segment sum
__device__ unsigned g_maxe[NN*CH];      // segment max: order-preserving uint encoding, later decoded to float in place
__device__ float    g_deg[NN];
__device__ float    g_amp[NN];
__device__ float    g_att[NN];
__device__ float    g_inv[NN];
__device__ float    g_logsum;
__device__ float    g_degref;

// order-preserving float<->uint map: unsigned compare == float compare
__device__ __forceinline__ unsigned encf(float f){
    unsigned u = __float_as_uint(f);
    return (u & 0x80000000u) ? ~u : (u | 0x80000000u);
}
__device__ __forceinline__ float decf(unsigned u){
    return __uint_as_float((u & 0x80000000u) ? (u & 0x7fffffffu) : ~u);
}
// encf(-inf) = ~0xff800000 = 0x007fffff
#define ENC_NEG_INF 0x007fffffu

// ---------------- init ----------------
__global__ void k_init(){
    int i = blockIdx.x*blockDim.x + threadIdx.x;
    if(i < NN*CH){ g_sum[i] = 0.f; g_maxe[i] = ENC_NEG_INF; }
    if(i < NN) g_deg[i] = 0.f;
    if(i == 0) g_logsum = 0.f;
}

// ---------------- edge scatter: one warp per edge ----------------
// edge_index is int32 on device (JAX default config downcasts int64 -> int32).
__global__ void __launch_bounds__(256) k_edge(const float* __restrict__ x,
                                              const int* __restrict__ ei){
    int gtid = blockIdx.x*blockDim.x + threadIdx.x;
    int e    = gtid >> 5;
    int lane = gtid & 31;
    if(e >= NE) return;
    int src = ei[e];
    int dst = ei[NE + e];
    float4 v = *(const float4*)(x + (size_t)src*CH + lane*4);
    float* s = g_sum + (size_t)dst*CH + lane*4;
    atomicAdd(s+0, v.x); atomicAdd(s+1, v.y);
    atomicAdd(s+2, v.z); atomicAdd(s+3, v.w);
    unsigned* m = g_maxe + (size_t)dst*CH + lane*4;
    atomicMax(m+0, encf(v.x)); atomicMax(m+1, encf(v.y));
    atomicMax(m+2, encf(v.z)); atomicMax(m+3, encf(v.w));
    if(lane == 0) atomicAdd(&g_deg[dst], 1.0f);
}

// ---------------- degree_reference reduction ----------------
__global__ void k_degsum(){
    __shared__ float sh[256];
    int i = blockIdx.x*256 + threadIdx.x;
    float v = (i < NN) ? log1pf(g_deg[i] + 1.0f) : 0.f;
    sh[threadIdx.x] = v;
    __syncthreads();
    for(int s = 128; s > 0; s >>= 1){
        if(threadIdx.x < s) sh[threadIdx.x] += sh[threadIdx.x + s];
        __syncthreads();
    }
    if(threadIdx.x == 0) atomicAdd(&g_logsum, sh[0]);
}

__global__ void k_ref(){ g_degref = fmaxf(g_logsum / (float)NN, 1.0f); }

__global__ void k_node(){
    int i = blockIdx.x*blockDim.x + threadIdx.x;
    if(i < NN){
        float d  = g_deg[i];
        float dt = log1pf(d + 1.0f);
        float r  = g_degref;
        g_amp[i] = dt / r;
        g_att[i] = r / fmaxf(dt, 1e-6f);
        g_inv[i] = 1.0f / fmaxf(d, 1.0f);
    }
}

// decode encoded max in place to float (0 where degree==0)
__global__ void k_dec(){
    int i = blockIdx.x*blockDim.x + threadIdx.x;
    if(i < NN*CH){
        float d = g_deg[i >> 7];
        float v = (d > 0.f) ? decf(g_maxe[i]) : 0.f;
        g_maxe[i] = __float_as_uint(v);
    }
}

// ---------------- fused GEMM ----------------
// out[n,o] = sum_{k<1152} F[n,k]*Wm[o,k] + sum_{k<128} x[n,k]*Wr[o,k] + bm[o] + br[o]
// F synthesized on the fly: k -> feature block j=k>>7 (a = j/3 selects sum/mean/max,
// s = j%3 selects {1, amp, att}); BK=16 divides 128 so j is constant per k-tile.
#define BM 64
#define BN 128
#define BK 16
#define KTOT 1280

__global__ void __launch_bounds__(256) k_gemm(
    const float* __restrict__ x,  const float* __restrict__ Wm,
    const float* __restrict__ bm, const float* __restrict__ Wr,
    const float* __restrict__ br, float* __restrict__ out)
{
    __shared__ float As[BK][BM];
    __shared__ float Bs[BK][BN];
    __shared__ float s_amp[BM], s_att[BM], s_inv[BM];

    int tid = threadIdx.x;
    int n0  = blockIdx.x * BM;

    if(tid < BM){
        int n = n0 + tid;
        bool ok = n < NN;
        s_amp[tid] = ok ? g_amp[n] : 0.f;
        s_att[tid] = ok ? g_att[n] : 0.f;
        s_inv[tid] = ok ? g_inv[n] : 0.f;
    }
    __syncthreads();

    int tx = tid & 31;          // output group: o = tx*4 .. tx*4+3
    int ty = tid >> 5;          // node group:   n = n0 + ty*8 .. +7
    int ar = tid >> 2;          // A-loader node row (0..63)
    int ac = (tid & 3) * 4;     // A-loader k offset within tile
    int bo = tid >> 1;          // B-loader output row (0..127)
    int bk8 = (tid & 1) * 8;    // B-loader k offset within tile

    float acc[8][4];
    #pragma unroll
    for(int i=0;i<8;i++)
        #pragma unroll
        for(int j=0;j<4;j++) acc[i][j] = 0.f;

    for(int k0 = 0; k0 < KTOT; k0 += BK){
        // ---- A fragment (global -> regs) ----
        int n = n0 + ar;
        float4 av = make_float4(0.f,0.f,0.f,0.f);
        if(n < NN){
            if(k0 < 1152){
                int j = k0 >> 7;
                int a = j / 3;            // 0:sum 1:mean 2:max
                int sidx = j - 3*a;       // 0:id 1:amp 2:att
                int cb = (k0 & 127) + ac;
                const float* base = (a == 2) ? (const float*)g_maxe : g_sum;
                av = *(const float4*)(base + (size_t)n*CH + cb);
                float sc = (a == 1) ? s_inv[ar] : 1.0f;
                if(sidx == 1)      sc *= s_amp[ar];
                else if(sidx == 2) sc *= s_att[ar];
                av.x *= sc; av.y *= sc; av.z *= sc; av.w *= sc;
            } else {
                av = *(const float4*)(x + (size_t)n*CH + (k0 - 1152) + ac);
            }
        }
        // ---- B fragment (global -> regs) ----
        float4 b0, b1;
        if(k0 < 1152){
            const float* wp = Wm + (size_t)bo*1152 + k0 + bk8;
            b0 = *(const float4*)(wp);
            b1 = *(const float4*)(wp + 4);
        } else {
            const float* wp = Wr + (size_t)bo*CH + (k0 - 1152) + bk8;
            b0 = *(const float4*)(wp);
            b1 = *(const float4*)(wp + 4);
        }

        __syncthreads();
        As[ac+0][ar] = av.x; As[ac+1][ar] = av.y;
        As[ac+2][ar] = av.z; As[ac+3][ar] = av.w;
        Bs[bk8+0][bo] = b0.x; Bs[bk8+1][bo] = b0.y;
        Bs[bk8+2][bo] = b0.z; Bs[bk8+3][bo] = b0.w;
        Bs[bk8+4][bo] = b1.x; Bs[bk8+5][bo] = b1.y;
        Bs[bk8+6][bo] = b1.z; Bs[bk8+7][bo] = b1.w;
        __syncthreads();

        #pragma unroll
        for(int kk = 0; kk < BK; kk++){
            float4 a0 = *(const float4*)&As[kk][ty*8];
            float4 a1 = *(const float4*)&As[kk][ty*8 + 4];
            float4 b  = *(const float4*)&Bs[kk][tx*4];
            float aa[8] = {a0.x,a0.y,a0.z,a0.w,a1.x,a1.y,a1.z,a1.w};
            float bb[4] = {b.x,b.y,b.z,b.w};
            #pragma unroll
            for(int i=0;i<8;i++)
                #pragma unroll
                for(int j=0;j<4;j++)
                    acc[i][j] = fmaf(aa[i], bb[j], acc[i][j]);
        }
    }

    // ---- epilogue ----
    float4 bias;
    bias.x = bm[tx*4+0] + br[tx*4+0];
    bias.y = bm[tx*4+1] + br[tx*4+1];
    bias.z = bm[tx*4+2] + br[tx*4+2];
    bias.w = bm[tx*4+3] + br[tx*4+3];
    #pragma unroll
    for(int i=0;i<8;i++){
        int n = n0 + ty*8 + i;
        if(n < NN){
            float4 r;
            r.x = acc[i][0] + bias.x; r.y = acc[i][1] + bias.y;
            r.z = acc[i][2] + bias.z; r.w = acc[i][3] + bias.w;
            *(float4*)(out + (size_t)n*CH + tx*4) = r;
        }
    }
}

// ---------------- launch ----------------
extern "C" void kernel_launch(void* const* d_in, const int* in_sizes, int n_in,
                              void* d_out, int out_size)
{
    const float* x  = (const float*)d_in[0];
    const int*   ei = (const int*)d_in[1];
    const float* Wm = (const float*)d_in[2];
    const float* bm = (const float*)d_in[3];
    const float* Wr = (const float*)d_in[4];
    const float* br = (const float*)d_in[5];
    float* out = (float*)d_out;

    k_init  <<<(NN*CH + 255)/256, 256>>>();
    k_edge  <<<(NE*32 + 255)/256, 256>>>(x, ei);
    k_degsum<<<(NN + 255)/256,   256>>>();
    k_ref   <<<1, 1>>>();
    k_node  <<<(NN + 255)/256,   256>>>();
    k_dec   <<<(NN*CH + 255)/256, 256>>>();
    k_gemm  <<<(NN + BM - 1)/BM, 256>>>(x, Wm, bm, Wr, br, out);
}

// round 5
// speedup vs baseline: 1.5012x; 1.5012x over previous
#include <cuda_runtime.h>
#include <cstdint>

#define NN 50000
#define NE 600000
#define CH 128
#define NBLK ((NN + 255) / 256)   // 196 scan blocks

// ---------------- scratch (static device globals; no allocation) ----------------
__device__ float g_sum [NN*CH];     // segment sum   (fully written by k_agg)
__device__ float g_maxf[NN*CH];     // segment max   (fully written by k_agg)
__device__ int   g_hist[NN];        // in-degree
__device__ int   g_off [NN+1];      // CSR offsets (exclusive)
__device__ int   g_cur [NN];        // scatter cursors
__device__ int   g_offpart[NN];     // scan partials
__device__ int   g_bsum[NBLK];
__device__ int   g_bbase[NBLK];
__device__ int   g_srt [NE];        // src ids sorted by dst
__device__ float g_amp[NN];
__device__ float g_att[NN];
__device__ float g_inv[NN];
__device__ float g_logsum;
__device__ float g_degref;

// ---------------- zero (per-call: graph replays must be deterministic) ----------------
__global__ void k_zero(){
    int i = blockIdx.x*blockDim.x + threadIdx.x;
    if(i < NN) g_hist[i] = 0;
    if(i == 0) g_logsum = 0.f;
}

// ---------------- degree histogram ----------------
__global__ void __launch_bounds__(256) k_hist(const int* __restrict__ ei){
    int e = blockIdx.x*blockDim.x + threadIdx.x;
    if(e < NE) atomicAdd(&g_hist[ei[NE + e]], 1);
}

// ---------------- exclusive scan over g_hist -> g_off ----------------
__global__ void k_scan1(){
    __shared__ int sh[256];
    int i = blockIdx.x*256 + threadIdx.x;
    int v = (i < NN) ? g_hist[i] : 0;
    sh[threadIdx.x] = v;
    __syncthreads();
    #pragma unroll
    for(int off = 1; off < 256; off <<= 1){
        int t = (threadIdx.x >= off) ? sh[threadIdx.x - off] : 0;
        __syncthreads();
        sh[threadIdx.x] += t;
        __syncthreads();
    }
    if(i < NN) g_offpart[i] = sh[threadIdx.x] - v;
    if(threadIdx.x == 255) g_bsum[blockIdx.x] = sh[255];
}

__global__ void k_scan2(){
    __shared__ int sh[256];
    int t = threadIdx.x;
    int v = (t < NBLK) ? g_bsum[t] : 0;
    sh[t] = v;
    __syncthreads();
    #pragma unroll
    for(int off = 1; off < 256; off <<= 1){
        int u = (t >= off) ? sh[t - off] : 0;
        __syncthreads();
        sh[t] += u;
        __syncthreads();
    }
    if(t < NBLK) g_bbase[t] = sh[t] - v;
}

__global__ void k_scan3(){
    int i = blockIdx.x*blockDim.x + threadIdx.x;
    if(i < NN){
        int o = g_offpart[i] + g_bbase[i >> 8];
        g_off[i] = o;
        g_cur[i] = o;
    }
    if(i == 0) g_off[NN] = NE;
}

// ---------------- scatter src into dst-sorted order ----------------
__global__ void __launch_bounds__(256) k_scatter(const int* __restrict__ ei){
    int e = blockIdx.x*blockDim.x + threadIdx.x;
    if(e < NE){
        int src = ei[e];
        int dst = ei[NE + e];
        int pos = atomicAdd(&g_cur[dst], 1);
        g_srt[pos] = src;
    }
}

// ---------------- atomic-free aggregation: one warp per node ----------------
__global__ void __launch_bounds__(256) k_agg(const float* __restrict__ x){
    int gtid = blockIdx.x*blockDim.x + threadIdx.x;
    int node = gtid >> 5;
    int lane = gtid & 31;
    if(node >= NN) return;
    int beg = g_off[node];
    int end = g_off[node + 1];

    float4 s = make_float4(0.f, 0.f, 0.f, 0.f);
    const float NINF = __int_as_float(0xff800000);
    float4 m = make_float4(NINF, NINF, NINF, NINF);

    for(int b = beg; b < end; b += 32){
        int idx = b + lane;
        int my  = (idx < end) ? g_srt[idx] : 0;
        int cnt = min(32, end - b);
        #pragma unroll 4
        for(int j = 0; j < cnt; j++){
            int sj = __shfl_sync(0xffffffffu, my, j);
            float4 v = *(const float4*)(x + (size_t)sj*CH + lane*4);
            s.x += v.x; s.y += v.y; s.z += v.z; s.w += v.w;
            m.x = fmaxf(m.x, v.x); m.y = fmaxf(m.y, v.y);
            m.z = fmaxf(m.z, v.z); m.w = fmaxf(m.w, v.w);
        }
    }
    if(end == beg) m = make_float4(0.f, 0.f, 0.f, 0.f);   // empty segment -> 0
    size_t o = (size_t)node*CH + lane*4;
    *(float4*)(g_sum  + o) = s;
    *(float4*)(g_maxf + o) = m;
}

// ---------------- degree_reference + per-node scales ----------------
__global__ void k_degsum(){
    __shared__ float sh[256];
    int i = blockIdx.x*256 + threadIdx.x;
    float v = (i < NN) ? log1pf((float)g_hist[i] + 1.0f) : 0.f;
    sh[threadIdx.x] = v;
    __syncthreads();
    for(int s = 128; s > 0; s >>= 1){
        if(threadIdx.x < s) sh[threadIdx.x] += sh[threadIdx.x + s];
        __syncthreads();
    }
    if(threadIdx.x == 0) atomicAdd(&g_logsum, sh[0]);
}

__global__ void k_ref(){ g_degref = fmaxf(g_logsum / (float)NN, 1.0f); }

__global__ void k_node(){
    int i = blockIdx.x*blockDim.x + threadIdx.x;
    if(i < NN){
        float d  = (float)g_hist[i];
        float dt = log1pf(d + 1.0f);
        float r  = g_degref;
        g_amp[i] = dt / r;
        g_att[i] = r / fmaxf(dt, 1e-6f);
        g_inv[i] = 1.0f / fmaxf(d, 1.0f);
    }
}

// ---------------- fused GEMM ----------------
// out[n,o] = sum_{k<1152} F[n,k]*Wm[o,k] + sum_{k<128} x[n,k]*Wr[o,k] + bm[o] + br[o]
// F synthesized on the fly: feature block j=k>>7 (a=j/3 selects sum/mean/max,
// j%3 selects {1, amp, att}); BK=16 divides 128 so j is constant per k-tile.
#define BM 64
#define BN 128
#define BK 16
#define KTOT 1280

__global__ void __launch_bounds__(256) k_gemm(
    const float* __restrict__ x,  const float* __restrict__ Wm,
    const float* __restrict__ bm, const float* __restrict__ Wr,
    const float* __restrict__ br, float* __restrict__ out)
{
    __shared__ float As[BK][BM];
    __shared__ float Bs[BK][BN];
    __shared__ float s_amp[BM], s_att[BM], s_inv[BM];

    int tid = threadIdx.x;
    int n0  = blockIdx.x * BM;

    if(tid < BM){
        int n = n0 + tid;
        bool ok = n < NN;
        s_amp[tid] = ok ? g_amp[n] : 0.f;
        s_att[tid] = ok ? g_att[n] : 0.f;
        s_inv[tid] = ok ? g_inv[n] : 0.f;
    }
    __syncthreads();

    int tx = tid & 31;          // output group: o = tx*4 .. tx*4+3
    int ty = tid >> 5;          // node group:   n = n0 + ty*8 .. +7
    int ar = tid >> 2;          // A-loader node row (0..63)
    int ac = (tid & 3) * 4;     // A-loader k offset within tile
    int bo = tid >> 1;          // B-loader output row (0..127)
    int bk8 = (tid & 1) * 8;    // B-loader k offset within tile

    float acc[8][4];
    #pragma unroll
    for(int i=0;i<8;i++)
        #pragma unroll
        for(int j=0;j<4;j++) acc[i][j] = 0.f;

    for(int k0 = 0; k0 < KTOT; k0 += BK){
        // ---- A fragment (global -> regs) ----
        int n = n0 + ar;
        float4 av = make_float4(0.f,0.f,0.f,0.f);
        if(n < NN){
            if(k0 < 1152){
                int j = k0 >> 7;
                int a = j / 3;            // 0:sum 1:mean 2:max
                int sidx = j - 3*a;       // 0:id 1:amp 2:att
                int cb = (k0 & 127) + ac;
                const float* base = (a == 2) ? g_maxf : g_sum;
                av = *(const float4*)(base + (size_t)n*CH + cb);
                float sc = (a == 1) ? s_inv[ar] : 1.0f;
                if(sidx == 1)      sc *= s_amp[ar];
                else if(sidx == 2) sc *= s_att[ar];
                av.x *= sc; av.y *= sc; av.z *= sc; av.w *= sc;
            } else {
                av = *(const float4*)(x + (size_t)n*CH + (k0 - 1152) + ac);
            }
        }
        // ---- B fragment (global -> regs) ----
        float4 b0, b1;
        if(k0 < 1152){
            const float* wp = Wm + (size_t)bo*1152 + k0 + bk8;
            b0 = *(const float4*)(wp);
            b1 = *(const float4*)(wp + 4);
        } else {
            const float* wp = Wr + (size_t)bo*CH + (k0 - 1152) + bk8;
            b0 = *(const float4*)(wp);
            b1 = *(const float4*)(wp + 4);
        }

        __syncthreads();
        As[ac+0][ar] = av.x; As[ac+1][ar] = av.y;
        As[ac+2][ar] = av.z; As[ac+3][ar] = av.w;
        Bs[bk8+0][bo] = b0.x; Bs[bk8+1][bo] = b0.y;
        Bs[bk8+2][bo] = b0.z; Bs[bk8+3][bo] = b0.w;
        Bs[bk8+4][bo] = b1.x; Bs[bk8+5][bo] = b1.y;
        Bs[bk8+6][bo] = b1.z; Bs[bk8+7][bo] = b1.w;
        __syncthreads();

        #pragma unroll
        for(int kk = 0; kk < BK; kk++){
            float4 a0 = *(const float4*)&As[kk][ty*8];
            float4 a1 = *(const float4*)&As[kk][ty*8 + 4];
            float4 b  = *(const float4*)&Bs[kk][tx*4];
            float aa[8] = {a0.x,a0.y,a0.z,a0.w,a1.x,a1.y,a1.z,a1.w};
            float bb[4] = {b.x,b.y,b.z,b.w};
            #pragma unroll
            for(int i=0;i<8;i++)
                #pragma unroll
                for(int j=0;j<4;j++)
                    acc[i][j] = fmaf(aa[i], bb[j], acc[i][j]);
        }
    }

    // ---- epilogue ----
    float4 bias;
    bias.x = bm[tx*4+0] + br[tx*4+0];
    bias.y = bm[tx*4+1] + br[tx*4+1];
    bias.z = bm[tx*4+2] + br[tx*4+2];
    bias.w = bm[tx*4+3] + br[tx*4+3];
    #pragma unroll
    for(int i=0;i<8;i++){
        int n = n0 + ty*8 + i;
        if(n < NN){
            float4 r;
            r.x = acc[i][0] + bias.x; r.y = acc[i][1] + bias.y;
            r.z = acc[i][2] + bias.z; r.w = acc[i][3] + bias.w;
            *(float4*)(out + (size_t)n*CH + tx*4) = r;
        }
    }
}

// ---------------- launch ----------------
extern "C" void kernel_launch(void* const* d_in, const int* in_sizes, int n_in,
                              void* d_out, int out_size)
{
    const float* x  = (const float*)d_in[0];
    const int*   ei = (const int*)d_in[1];
    const float* Wm = (const float*)d_in[2];
    const float* bm = (const float*)d_in[3];
    const float* Wr = (const float*)d_in[4];
    const float* br = (const float*)d_in[5];
    float* out = (float*)d_out;

    k_zero   <<<(NN + 255)/256, 256>>>();
    k_hist   <<<(NE + 255)/256, 256>>>(ei);
    k_scan1  <<<NBLK, 256>>>();
    k_scan2  <<<1, 256>>>();
    k_scan3  <<<NBLK, 256>>>();
    k_scatter<<<(NE + 255)/256, 256>>>(ei);
    k_agg    <<<(NN*32 + 255)/256, 256>>>(x);
    k_degsum <<<(NN + 255)/256, 256>>>();
    k_ref    <<<1, 1>>>();
    k_node   <<<(NN + 255)/256, 256>>>();
    k_gemm   <<<(NN + BM - 1)/BM, 256>>>(x, Wm, bm, Wr, br, out);
}